// round 11
// baseline (speedup 1.0000x reference)
#include <cuda_runtime.h>
#include <cstdint>

// Problem constants
#define B_   4
#define TE   512
#define TD   256
#define DE   512
#define DD   512
#define U_   128
#define NROW_E (B_*TE)   // 2048 encoder rows
#define NROW_D (B_*TD)   // 1024 decoder rows
#define TT   4           // decoder-t tile per attn block
#define CTX_OFF (NROW_D*DE)   // context elements before attn weights in d_out

typedef unsigned long long ull;

// Scratch (static device globals: no allocation allowed)
__device__ float g_encT[U_ * NROW_E];   // enc projection, TRANSPOSED: [u][row]
__device__ float g_dec [NROW_D * U_];   // dec projection: [row][u]

__device__ __forceinline__ float tanh_fast(float x) {
    float y;
    asm("tanh.approx.f32 %0, %1;" : "=f"(y) : "f"(x));
    return y;
}

#define FMA_F32X2(d, a, b) \
    asm("fma.rn.f32x2 %0, %1, %2, %0;" : "+l"(d) : "l"(a), "l"(b))

__device__ __forceinline__ ull pack2(float lo, float hi) {
    ull r;
    asm("mov.b64 %0, {%1, %2};" : "=l"(r) : "f"(lo), "f"(hi));
    return r;
}

// ---------------------------------------------------------------------------
// Kernel 1: both projections, balanced mixed blocks + f32x2 row pairs.
// Grid: 128 blocks x 512 threads. Block = 16 enc rows + 8 dec rows = 12 pairs.
//   rg0: enc pairs 0-3 (W1)   rg1: enc pairs 4-7 (W1)
//   rg2: dec pairs 8-9 (W2)   rg3: dec pairs 10-11 (W2)
// X transposed into smem as row-pairs (sXP[k][pair]); per k the hot loop is
// LDG(w) + pack + 2 LDS.128 + 4 FFMA2 = 8 instr for 8 rows.
// ---------------------------------------------------------------------------
#define PKC 128        // k-chunk
#define PSTRIDE 14     // padded pair stride (float2 units; 112B, 16B-aligned)

__global__ __launch_bounds__(512) void proj_kernel(
    const float* __restrict__ enc, const float* __restrict__ dec,
    const float* __restrict__ W1, const float* __restrict__ b1,
    const float* __restrict__ W2, const float* __restrict__ b2)
{
    __shared__ __align__(16) float2 sXP[PKC * PSTRIDE];

    int blk  = blockIdx.x;           // 0..127
    int rowE = blk * 16;             // 16 enc rows
    int rowD = blk * 8;              // 8 dec rows
    int tid  = threadIdx.x;
    int u    = tid & 127;
    int rg   = tid >> 7;             // 0..3 (uniform per warp)

    const float* W  = (rg < 2) ? W1 : W2;
    float bv        = (rg < 2) ? b1[u] : b2[u];
    int pbase       = rg * 4 - ((rg >= 2) ? 4 : 0) + ((rg == 3) ? -2 : 0);
    // rg0->0, rg1->4, rg2->8, rg3->10
    pbase = (rg == 0) ? 0 : (rg == 1) ? 4 : (rg == 2) ? 8 : 10;

    ull acc[4];
#pragma unroll
    for (int p = 0; p < 4; p++) acc[p] = pack2(bv, bv);

    for (int kc = 0; kc < 512; kc += PKC) {
        __syncthreads();
        // fill transposed pairs: 24 rows x 32 k-quads = 768 units
        for (int idx = tid; idx < 24 * 32; idx += 512) {
            int r = idx >> 5, kq = idx & 31;
            const float* src = (r < 16)
                ? (enc + (size_t)(rowE + r) * 512)
                : (dec + (size_t)(rowD + r - 16) * 512);
            float4 v = *(const float4*)(src + kc + kq * 4);
            int pair = r >> 1, h = r & 1;
            ((float*)&sXP[(kq * 4 + 0) * PSTRIDE + pair])[h] = v.x;
            ((float*)&sXP[(kq * 4 + 1) * PSTRIDE + pair])[h] = v.y;
            ((float*)&sXP[(kq * 4 + 2) * PSTRIDE + pair])[h] = v.z;
            ((float*)&sXP[(kq * 4 + 3) * PSTRIDE + pair])[h] = v.w;
        }
        __syncthreads();

        const float* Wp = W + (size_t)kc * U_ + u;
        if (rg < 2) {
#pragma unroll 4
            for (int kk = 0; kk < PKC; kk++) {
                float wv = Wp[(size_t)kk * U_];     // coalesced LDG
                ull  ww  = pack2(wv, wv);
                const ulonglong2* xb =
                    (const ulonglong2*)&sXP[kk * PSTRIDE + pbase];
                ulonglong2 x01 = xb[0];             // pairs pbase, pbase+1
                ulonglong2 x23 = xb[1];             // pairs pbase+2, pbase+3
                FMA_F32X2(acc[0], x01.x, ww);
                FMA_F32X2(acc[1], x01.y, ww);
                FMA_F32X2(acc[2], x23.x, ww);
                FMA_F32X2(acc[3], x23.y, ww);
            }
        } else {
#pragma unroll 4
            for (int kk = 0; kk < PKC; kk++) {
                float wv = Wp[(size_t)kk * U_];
                ull  ww  = pack2(wv, wv);
                const ulonglong2* xb =
                    (const ulonglong2*)&sXP[kk * PSTRIDE + pbase];
                ulonglong2 x01 = xb[0];
                FMA_F32X2(acc[0], x01.x, ww);
                FMA_F32X2(acc[1], x01.y, ww);
            }
        }
    }

    if (rg < 2) {
        // enc: rows rowE + 2*(pbase+p) .. +1, consecutive in g_encT[u][row]
#pragma unroll
        for (int p = 0; p < 4; p++)
            *(ull*)&g_encT[(size_t)u * NROW_E + rowE + 2 * (pbase + p)] = acc[p];
    } else {
#pragma unroll
        for (int p = 0; p < 2; p++) {
            float lo, hi;
            asm("mov.b64 {%0, %1}, %2;" : "=f"(lo), "=f"(hi) : "l"(acc[p]));
            int row = rowD + 2 * (pbase + p) - 16;
            g_dec[(size_t)row * U_ + u]       = lo;
            g_dec[(size_t)(row + 1) * U_ + u] = hi;
        }
    }
}

// ---------------------------------------------------------------------------
// Kernel 2: fused score + softmax + context (R7-proven structure).
// Grid: B * (TD/TT) = 256 blocks, 1024 threads, 2 blocks/SM.
//   Score: thread = (e, half); half owns 2 t's; per u: LDG ev + one LDS.128
//          broadcast of {dp_t0, dp_t1, vv} (sV folded into the tile).
//   Context: thread = (d, half); half owns 256 e's; partials via s_w.
// ---------------------------------------------------------------------------
__global__ __launch_bounds__(1024, 2) void attn_kernel(
    const float* __restrict__ enc,
    const float* __restrict__ Vw,
    float* __restrict__ out)
{
    __shared__ __align__(16) float sdpv[U_ * 8];  // [u][half]{dp0,dp1,vv,pad}
    __shared__ float sred[TT * 16];
    __shared__ float smax[TT];
    __shared__ float ssum[TT];
    __shared__ __align__(16) float s_w[TE][TT];   // weights -> ctx partials

    int b  = blockIdx.x >> 6;                // / (TD/TT = 64)
    int t0 = (blockIdx.x & 63) * TT;
    int tid  = threadIdx.x;
    int half = tid >> 9;                     // 0 or 1
    int eth  = tid & 511;                    // e (score) / d (context)
    const int tb = half * 2;                 // this half's t pair

    // fill sdpv: dp components + vv (disjoint addresses, no race)
    if (tid < TT * U_) {
        int t = tid >> 7, u = tid & 127;
        float dv = g_dec[(size_t)(b * TD + t0) * U_ + tid];  // coalesced
        sdpv[u * 8 + (t >> 1) * 4 + (t & 1)] = dv;
    }
    if (tid < U_) {
        float vv = Vw[tid];
        sdpv[tid * 8 + 2] = vv;
        sdpv[tid * 8 + 6] = vv;
    }
    __syncthreads();

    // ---- score phase: thread owns e = eth, t in [tb, tb+2) ----
    float acc0 = 0.f, acc1 = 0.f;
    const float* ep = g_encT + (size_t)b * TE + eth;
#pragma unroll 4
    for (int u = 0; u < U_; u++) {
        float  ev = ep[(size_t)u * NROW_E];               // coalesced, L2-res.
        float4 q  = *(const float4*)&sdpv[u * 8 + half * 4]; // broadcast LDS.128
        acc0 += q.z * tanh_fast(ev + q.x);
        acc1 += q.z * tanh_fast(ev + q.y);
    }
    // (V_b dropped: softmax is shift-invariant; cancels in both outputs)

    // ---- softmax over e (512 threads per half), per t ----
    int lane = tid & 31, wid = tid >> 5;     // 32 warps
    int wloc = wid & 15;                     // warp index within half

    // max
    {
        float v0 = acc0, v1 = acc1;
#pragma unroll
        for (int o = 16; o; o >>= 1) {
            v0 = fmaxf(v0, __shfl_xor_sync(0xffffffffu, v0, o));
            v1 = fmaxf(v1, __shfl_xor_sync(0xffffffffu, v1, o));
        }
        if (lane == 0) {
            sred[(tb + 0) * 16 + wloc] = v0;
            sred[(tb + 1) * 16 + wloc] = v1;
        }
    }
    __syncthreads();
    if (wid < TT) {
        float v = (lane < 16) ? sred[wid * 16 + lane] : -3.0e38f;
#pragma unroll
        for (int o = 8; o; o >>= 1)
            v = fmaxf(v, __shfl_xor_sync(0xffffffffu, v, o));
        if (lane == 0) smax[wid] = v;
    }
    __syncthreads();

    // exp + sum
    float p0 = __expf(acc0 - smax[tb + 0]);
    float p1 = __expf(acc1 - smax[tb + 1]);
    {
        float v0 = p0, v1 = p1;
#pragma unroll
        for (int o = 16; o; o >>= 1) {
            v0 += __shfl_xor_sync(0xffffffffu, v0, o);
            v1 += __shfl_xor_sync(0xffffffffu, v1, o);
        }
        if (lane == 0) {
            sred[(tb + 0) * 16 + wloc] = v0;
            sred[(tb + 1) * 16 + wloc] = v1;
        }
    }
    __syncthreads();
    if (wid < TT) {
        float v = (lane < 16) ? sred[wid * 16 + lane] : 0.f;
#pragma unroll
        for (int o = 8; o; o >>= 1)
            v += __shfl_xor_sync(0xffffffffu, v, o);
        if (lane == 0) ssum[wid] = v;
    }
    __syncthreads();

    // weights -> smem [e][t] (for context) and gmem output
    {
        float w0 = p0 / ssum[tb + 0];
        float w1 = p1 / ssum[tb + 1];
        *(float2*)&s_w[eth][tb] = make_float2(w0, w1);
        out[CTX_OFF + (size_t)(b * TD + t0 + tb + 0) * TE + eth] = w0;
        out[CTX_OFF + (size_t)(b * TD + t0 + tb + 1) * TE + eth] = w1;
    }
    __syncthreads();

    // ---- context phase: thread owns d = eth, e-range [half*256, +256) ----
    const float* eb = enc + ((size_t)b * TE + half * 256) * DE + eth;

    ull cc0 = 0ULL, cc1 = 0ULL;
#pragma unroll 4
    for (int ei = 0; ei < 256; ei++) {
        float ev = __ldg(eb + (size_t)ei * DE);     // coalesced, L2-resident
        ull evv = pack2(ev, ev);
        ulonglong2 q = *(const ulonglong2*)&s_w[half * 256 + ei][0];
        FMA_F32X2(cc0, q.x, evv);
        FMA_F32X2(cc1, q.y, evv);
    }

    float c[TT];
    asm("mov.b64 {%0, %1}, %2;" : "=f"(c[0]), "=f"(c[1]) : "l"(cc0));
    asm("mov.b64 {%0, %1}, %2;" : "=f"(c[2]), "=f"(c[3]) : "l"(cc1));

    // combine the two e-half partials through s_w (weights no longer needed)
    __syncthreads();
    if (half == 1)
        *(float4*)&s_w[eth][0] = make_float4(c[0], c[1], c[2], c[3]);
    __syncthreads();
    if (half == 0) {
        float4 o0 = *(float4*)&s_w[eth][0];
        c[0] += o0.x; c[1] += o0.y; c[2] += o0.z; c[3] += o0.w;
#pragma unroll
        for (int t = 0; t < TT; t++)
            out[(size_t)(b * TD + t0 + t) * DE + eth] = c[t];
    }
}

// ---------------------------------------------------------------------------
extern "C" void kernel_launch(void* const* d_in, const int* in_sizes, int n_in,
                              void* d_out, int out_size)
{
    (void)in_sizes; (void)n_in; (void)out_size;
    const float* enc = (const float*)d_in[0];
    const float* dec = (const float*)d_in[1];
    const float* W1  = (const float*)d_in[2];
    const float* b1  = (const float*)d_in[3];
    const float* W2  = (const float*)d_in[4];
    const float* b2  = (const float*)d_in[5];
    const float* Vw  = (const float*)d_in[6];
    // d_in[7] = V_b: unused (cancels in softmax)
    float* out = (float*)d_out;

    proj_kernel<<<128, 512>>>(enc, dec, W1, b1, W2, b2);
    attn_kernel<<<B_ * (TD / TT), 1024>>>(enc, Vw, out);
}